// round 1
// baseline (speedup 1.0000x reference)
#include <cuda_runtime.h>

#define NTIME 1024
#define NB    65536

__global__ void __launch_bounds__(256)
bts_interp_kernel(const float* __restrict__ times,
                  const float* __restrict__ values,
                  const float* __restrict__ tq,
                  float* __restrict__ out)
{
    const int b = blockIdx.x * blockDim.x + threadIdx.x;
    if (b >= NB) return;

    const float t = __ldg(&tq[b]);

    // count = upper_bound: number of i in [0,1024) with times[i,b] <= t.
    // Branchless binary lift; max reachable count = 1024 (step 1024 probes times[1023]).
    int c = 0;
#pragma unroll
    for (int step = NTIME; step >= 1; step >>= 1) {
        const int nc = c + step;
        if (nc <= NTIME) {
            const float knot = __ldg(&times[(size_t)(nc - 1) * NB + b]);
            if (knot <= t) c = nc;
        }
    }

    const int gi  = c & (NTIME - 1);                  // count mod 1024
    const int iv  = (gi + NTIME - 1) & (NTIME - 1);   // (gi-1) mod 1024
    int isl = gi - 1;                                 // (gi-1) mod 1023
    if (isl < 0) isl += (NTIME - 1);

    // Gather knot data. When gi>=1, iv == isl so these loads alias (L1/L2 dedups).
    const float t0 = __ldg(&times [(size_t)iv        * NB + b]);
    const float v0 = __ldg(&values[(size_t)iv        * NB + b]);
    const float ta = __ldg(&times [(size_t)isl       * NB + b]);
    const float tb = __ldg(&times [(size_t)(isl + 1) * NB + b]);
    const float va = __ldg(&values[(size_t)isl       * NB + b]);
    const float vb = __ldg(&values[(size_t)(isl + 1) * NB + b]);

    const float s0 = (vb - va) / (tb - ta);
    out[b] = v0 + s0 * (t - t0);
}

extern "C" void kernel_launch(void* const* d_in, const int* in_sizes, int n_in,
                              void* d_out, int out_size)
{
    const float* times  = (const float*)d_in[0];
    const float* values = (const float*)d_in[1];
    const float* tq     = (const float*)d_in[2];
    float* out = (float*)d_out;

    const int threads = 256;
    const int blocks  = NB / threads;
    bts_interp_kernel<<<blocks, threads>>>(times, values, tq, out);
}